// round 12
// baseline (speedup 1.0000x reference)
#include <cuda_runtime.h>
#include <cuda_bf16.h>
#include <cstdint>

// ---------------------------------------------------------------------------
// Problem constants
// ---------------------------------------------------------------------------
#define IMG_STRIDE 860672   // 512*41*41
#define KDIM 4608           // 512*9
#define NPAIR 40            // b*k = 8*5
#define SLEN 2000           // n*h*w = 5*400

// Static scratch (no dynamic allocation allowed)
__device__ __nv_bfloat16 g_nhwc[(size_t)208 * 1681 * 512];  // input, [img][px][ch] bf16
__device__ float    g_wF[KDIM * 256];                       // fused weights fp32, [k][n]
__device__ __nv_bfloat16 g_wS[9 * 16 * 256 * 32];           // fused weights bf16, [tap][cc][n][32ch]
__device__ uint32_t g_bufK[(size_t)208 * 400 * 128];        // K-proj, [img][px][ch], tf32 bits
__device__ float    g_bufV[(size_t)208 * 128 * 400];        // V-proj, [img][ch][px], fp32
__device__ __nv_bfloat16 g_bufVh[(size_t)208 * 128 * 400];  // V-proj bf16, [img][ch][px]
__device__ float    g_sim[(size_t)NPAIR * 400 * SLEN];      // sim, [pair][qpx][s]
__device__ __nv_bfloat16 g_attnB[(size_t)NPAIR * 400 * SLEN]; // attn bf16, [pair][qpx][s]
__device__ float    g_outT[(size_t)NPAIR * 128 * 400];      // attn@V, [pair][ch][px]

__device__ __forceinline__ uint32_t f2tf(float x) {
    uint32_t r;
    asm("cvt.rna.tf32.f32 %0, %1;" : "=r"(r) : "f"(x));
    return r;
}

__device__ __forceinline__ void cpa16(uint32_t dst, const void* src) {
    asm volatile("cp.async.cg.shared.global [%0], [%1], 16;\n" :: "r"(dst), "l"(src));
}
__device__ __forceinline__ void cpa_commit() { asm volatile("cp.async.commit_group;\n"); }
__device__ __forceinline__ void cpa_wait2() { asm volatile("cp.async.wait_group 2;\n"); }

__device__ __forceinline__ void ldsm4(uint32_t* d, uint32_t addr) {
    asm volatile("ldmatrix.sync.aligned.m8n8.x4.shared.b16 {%0,%1,%2,%3}, [%4];\n"
                 : "=r"(d[0]), "=r"(d[1]), "=r"(d[2]), "=r"(d[3]) : "r"(addr));
}

// tf32 m16n8k8 (sim GEMM)
__device__ __forceinline__ void mma8(float* c, const uint32_t* a, const uint32_t* b) {
    asm volatile(
        "mma.sync.aligned.m16n8k8.row.col.f32.tf32.tf32.f32 "
        "{%0,%1,%2,%3},{%4,%5,%6,%7},{%8,%9},{%0,%1,%2,%3};\n"
        : "+f"(c[0]), "+f"(c[1]), "+f"(c[2]), "+f"(c[3])
        : "r"(a[0]), "r"(a[1]), "r"(a[2]), "r"(a[3]), "r"(b[0]), "r"(b[1]));
}

// bf16 m16n8k16 (conv + out mainloops)
__device__ __forceinline__ void mma16(float* c, const uint32_t* a, const uint32_t* b) {
    asm volatile(
        "mma.sync.aligned.m16n8k16.row.col.f32.bf16.bf16.f32 "
        "{%0,%1,%2,%3},{%4,%5,%6,%7},{%8,%9},{%0,%1,%2,%3};\n"
        : "+f"(c[0]), "+f"(c[1]), "+f"(c[2]), "+f"(c[3])
        : "r"(a[0]), "r"(a[1]), "r"(a[2]), "r"(a[3]), "r"(b[0]), "r"(b[1]));
}

// Warp computes a 64x32 tile of C from As[16][128] x Bs[16][128] (tf32 k-major smem).
__device__ __forceinline__ void mma_block(const uint32_t (*As)[132], const uint32_t (*Bs)[132],
                                          float acc[4][4][4], int wm, int wn, int lane) {
    int r = lane >> 2, t = lane & 3;
#pragma unroll
    for (int ks = 0; ks < 2; ks++) {
        int kb = ks * 8;
        uint32_t a[4][4], b[4][2];
#pragma unroll
        for (int mi = 0; mi < 4; mi++) {
            int mb = wm * 64 + mi * 16 + r;
            a[mi][0] = As[kb + t][mb];
            a[mi][1] = As[kb + t][mb + 8];
            a[mi][2] = As[kb + t + 4][mb];
            a[mi][3] = As[kb + t + 4][mb + 8];
        }
#pragma unroll
        for (int ni = 0; ni < 4; ni++) {
            int nb = wn * 32 + ni * 8 + r;
            b[ni][0] = Bs[kb + t][nb];
            b[ni][1] = Bs[kb + t + 4][nb];
        }
#pragma unroll
        for (int mi = 0; mi < 4; mi++)
#pragma unroll
            for (int ni = 0; ni < 4; ni++)
                mma8(acc[mi][ni], a[mi], b[ni]);
    }
}

// ---------------------------------------------------------------------------
// 0) NCHW fp32 -> NHWC bf16 transpose. grid (53, 16, 208), block (32, 8).
// ---------------------------------------------------------------------------
__global__ void __launch_bounds__(256) nhwc_kernel(const float* __restrict__ q,
                                                   const float* __restrict__ s) {
    __shared__ float tile[32][33];
    int img = blockIdx.z;
    int px0 = blockIdx.x * 32, c0 = blockIdx.y * 32;
    const float* src = (img < 8) ? (q + (size_t)img * IMG_STRIDE)
                                 : (s + (size_t)(img - 8) * IMG_STRIDE);
    int tx = threadIdx.x, ty = threadIdx.y;
#pragma unroll
    for (int i = 0; i < 4; i++) {
        int c = c0 + ty + i * 8, px = px0 + tx;
        if (px < 1681) tile[ty + i * 8][tx] = src[(size_t)c * 1681 + px];
    }
    __syncthreads();
#pragma unroll
    for (int i = 0; i < 4; i++) {
        int px = px0 + ty + i * 8, c = c0 + tx;
        if (px < 1681)
            g_nhwc[((size_t)img * 1681 + px) * 512 + c] = __float2bfloat16(tile[tx][ty + i * 8]);
    }
}

// ---------------------------------------------------------------------------
// 1) Fuse weights: wF[k][n] = sum_e proj[n][e] * w_ms[e*4608 + k]
// ---------------------------------------------------------------------------
__global__ void __launch_bounds__(256) fuse_kernel(const float* __restrict__ wqk,
                                                   const float* __restrict__ wv,
                                                   const float* __restrict__ wms) {
    __shared__ float projS[256][17];
    __shared__ float msS[16][17];
    int tid = threadIdx.x;
    int k0 = blockIdx.x * 16;
    const float* prow = (tid < 128) ? (wqk + (size_t)tid * 512)
                                    : (wv + (size_t)(tid - 128) * 512);
    float acc[16];
#pragma unroll
    for (int i = 0; i < 16; i++) acc[i] = 0.f;

    int le = tid >> 4, lk = tid & 15;
    for (int e0 = 0; e0 < 512; e0 += 16) {
        __syncthreads();
#pragma unroll
        for (int q4 = 0; q4 < 4; q4++) {
            float4 d = *(const float4*)(prow + e0 + q4 * 4);
            projS[tid][q4 * 4 + 0] = d.x;
            projS[tid][q4 * 4 + 1] = d.y;
            projS[tid][q4 * 4 + 2] = d.z;
            projS[tid][q4 * 4 + 3] = d.w;
        }
        msS[le][lk] = wms[(size_t)(e0 + le) * KDIM + k0 + lk];
        __syncthreads();
#pragma unroll
        for (int e = 0; e < 16; e++) {
            float a = projS[tid][e];
#pragma unroll
            for (int kk = 0; kk < 16; kk++) acc[kk] += a * msS[e][kk];
        }
    }
#pragma unroll
    for (int kk = 0; kk < 16; kk++)
        g_wF[(size_t)(k0 + kk) * 256 + tid] = acc[kk];
}

// ---------------------------------------------------------------------------
// 1b) Repack weights to stage-major bf16 [tap][cc][n][32ch].
//     Channel c = cc*32 + c0; original k = c*9 + tap. grid 4608 x 256.
// ---------------------------------------------------------------------------
__global__ void __launch_bounds__(256) repack_kernel() {
    int idx = blockIdx.x * 256 + threadIdx.x;   // < 9*16*256*32 = 1179648
    int c0 = idx & 31;
    int n = (idx >> 5) & 255;
    int cc = (idx >> 13) & 15;
    int tap = idx >> 17;
    if (tap >= 9) return;
    int c = cc * 32 + c0;
    g_wS[idx] = __float2bfloat16(g_wF[(size_t)(c * 9 + tap) * 256 + n]);
}

// ---------------------------------------------------------------------------
// 2) Implicit-GEMM conv (bf16 HMMA, 4-buffer cp.async pipeline, 1 sync/stage):
//    grid 650 m-tiles, 512 threads (16 warps), BM=128, BN=256, BK=32,
//    warp tile 64x32. A and B operands via ldmatrix; B gmem stream is
//    stage-contiguous (16KB/stage, fully coalesced).
// ---------------------------------------------------------------------------
#define CNSTG 144
#define A_STG 10240          // 128*40*2 bytes per A stage
#define B_STG 20480          // 256*40*2 bytes per B stage

struct ConvSmem {
    __nv_bfloat16 A[4][128][40];   // [m][ch], +8 pad (80B pitch, 16-aligned)
    __nv_bfloat16 B[4][256][40];   // [n][ch], +8 pad (80B pitch, 16-aligned)
};

__global__ void __launch_bounds__(512) conv_kernel() {
    extern __shared__ __align__(16) char smem_raw[];
    ConvSmem& sm = *reinterpret_cast<ConvSmem*>(smem_raw);

    int tid = threadIdx.x, lane = tid & 31, warp = tid >> 5;
    int wm = warp & 1, wn = warp >> 1;
    int r = lane >> 2, t = lane & 3;

    // A-load: one 16B cp.async per thread per stage
    int arow = tid >> 2, aseg = tid & 3;
    const __nv_bfloat16* apix;
    {
        int m = blockIdx.x * 128 + arow;
        int img = m / 400;
        int p = m - img * 400;
        int oy = p / 20, ox = p - oy * 20;
        apix = g_nhwc + ((size_t)img * 1681 + (size_t)(2 * oy) * 41 + 2 * ox) * 512 + aseg * 8;
    }
    uint32_t aDst = (uint32_t)__cvta_generic_to_shared(&sm.A[0][arow][aseg * 8]);

    // B-load: 2 x 16B per thread, contiguous 32B. n = tid&255, bhi = ch-half.
    int bn = tid & 255, bhi = tid >> 8;
    uint32_t bDst = (uint32_t)__cvta_generic_to_shared(&sm.B[0][bn][bhi * 16]);

    float acc[4][4][4];
#pragma unroll
    for (int i = 0; i < 4; i++)
#pragma unroll
        for (int j = 0; j < 4; j++)
#pragma unroll
            for (int c = 0; c < 4; c++) acc[i][j][c] = 0.f;

    auto issue = [&](int s) {
        int buf = s & 3;
        int tap = s >> 4;
        int dy = tap / 3, dx = tap - 3 * dy;
        int po = (dy * 41 + dx) * 512 + ((s & 15) << 5);
        cpa16(aDst + buf * A_STG, apix + po);
        // stage-contiguous B: [tap][s&15][n][32ch]
        const __nv_bfloat16* bs = g_wS + (size_t)tap * 131072 + (size_t)(s & 15) * 8192
                                  + bn * 32 + bhi * 16;
        cpa16(bDst + buf * B_STG, bs);
        cpa16(bDst + buf * B_STG + 16, bs + 8);
    };

    issue(0); cpa_commit();
    issue(1); cpa_commit();

    uint32_t aLd = (uint32_t)__cvta_generic_to_shared(
        &sm.A[0][wm * 64 + (lane & 15)][(lane >> 4) * 8]);
    uint32_t bLd = (uint32_t)__cvta_generic_to_shared(
        &sm.B[0][wn * 32 + (lane & 7) + ((lane >> 4) & 1) * 8][0]) + ((lane >> 3) & 1) * 16;

    for (int s = 0; s < CNSTG; s++) {
        int buf = s & 3;
        if (s + 2 < CNSTG) issue(s + 2);
        cpa_commit();
        cpa_wait2();
        __syncthreads();

#pragma unroll
        for (int ks = 0; ks < 2; ks++) {
            uint32_t a[4][4];
#pragma unroll
            for (int mi = 0; mi < 4; mi++)
                ldsm4(a[mi], aLd + buf * A_STG + mi * 1280 + ks * 32);
            uint32_t b[4][2];
#pragma unroll
            for (int h = 0; h < 2; h++) {
                uint32_t d[4];
                ldsm4(d, bLd + buf * B_STG + h * 1280 + ks * 32);
                b[2 * h][0] = d[0];
                b[2 * h][1] = d[1];
                b[2 * h + 1][0] = d[2];
                b[2 * h + 1][1] = d[3];
            }
#pragma unroll
            for (int mi = 0; mi < 4; mi++)
#pragma unroll
                for (int ni = 0; ni < 4; ni++)
                    mma16(acc[mi][ni], a[mi], b[ni]);
        }
    }

    // Epilogue: cols 0..127 -> K-proj (tf32, px-major); 128..255 -> V (fp32 + bf16, ch-major)
#pragma unroll
    for (int mi = 0; mi < 4; mi++)
#pragma unroll
        for (int ni = 0; ni < 4; ni++)
#pragma unroll
            for (int ci = 0; ci < 4; ci++) {
                int row = blockIdx.x * 128 + wm * 64 + mi * 16 + r + ((ci & 2) ? 8 : 0);
                int col = wn * 32 + ni * 8 + 2 * t + (ci & 1);
                int im = row / 400;
                int pp = row - im * 400;
                float v = acc[mi][ni][ci];
                if (col < 128) {
                    g_bufK[((size_t)im * 400 + pp) * 128 + col] = f2tf(v);
                } else {
                    size_t o = ((size_t)im * 128 + (col - 128)) * 400 + pp;
                    g_bufV[o] = v;
                    g_bufVh[o] = __float2bfloat16(v);
                }
            }
}

// ---------------------------------------------------------------------------
// 3) sim[pair][400][2000] = (Q[400,128] @ K^T[128,2000]) * 128^-0.5
// ---------------------------------------------------------------------------
__global__ void __launch_bounds__(256) sim_kernel() {
    __shared__ uint32_t As[16][132];
    __shared__ uint32_t Bs[16][132];
    int tid = threadIdx.x, lane = tid & 31, warp = tid >> 5;
    int wm = warp & 1, wn = warp >> 1;
    int pair = blockIdx.z;
    int b = pair / 5;
    const uint32_t* Q = g_bufK + (size_t)b * 400 * 128;
    const uint32_t* Kp = g_bufK + (size_t)(8 + pair * 5) * 400 * 128;
    int m0 = blockIdx.y * 128, n0 = blockIdx.x * 128;

    float acc[4][4][4];
#pragma unroll
    for (int i = 0; i < 4; i++)
#pragma unroll
        for (int j = 0; j < 4; j++)
#pragma unroll
            for (int c = 0; c < 4; c++) acc[i][j][c] = 0.f;

    for (int k0 = 0; k0 < 128; k0 += 16) {
#pragma unroll
        for (int i = 0; i < 2; i++) {
            int v = tid + 256 * i;
            int l = v >> 2, kq = v & 3;
            uint4 d = make_uint4(0u, 0u, 0u, 0u);
            if (m0 + l < 400) d = *(const uint4*)(Q + (size_t)(m0 + l) * 128 + k0 + kq * 4);
            As[kq * 4 + 0][l] = d.x;
            As[kq * 4 + 1][l] = d.y;
            As[kq * 4 + 2][l] = d.z;
            As[kq * 4 + 3][l] = d.w;
        }
#pragma unroll
        for (int i = 0; i < 2; i++) {
            int v = tid + 256 * i;
            int l = v >> 2, kq = v & 3;
            uint4 d = make_uint4(0u, 0u, 0u, 0u);
            if (n0 + l < SLEN) d = *(const uint4*)(Kp + (size_t)(n0 + l) * 128 + k0 + kq * 4);
            Bs[kq * 4 + 0][l] = d.x;
            Bs[kq * 4 + 1][l] = d.y;
            Bs[kq * 4 + 2][l] = d.z;
            Bs[kq * 4 + 3][l] = d.w;
        }
        __syncthreads();
        mma_block(As, Bs, acc, wm, wn, lane);
        __syncthreads();
    }

    const float scale = 0.08838834764831845f;  // 128^-0.5
    int r = lane >> 2, t = lane & 3;
    float* simp = g_sim + (size_t)pair * 400 * SLEN;
#pragma unroll
    for (int mi = 0; mi < 4; mi++)
#pragma unroll
        for (int ni = 0; ni < 4; ni++)
#pragma unroll
            for (int ci = 0; ci < 4; ci++) {
                int row = m0 + wm * 64 + mi * 16 + r + ((ci & 2) ? 8 : 0);
                int col = n0 + wn * 32 + ni * 8 + 2 * t + (ci & 1);
                if (row < 400 && col < SLEN)
                    simp[(size_t)row * SLEN + col] = acc[mi][ni][ci] * scale;
            }
}

// ---------------------------------------------------------------------------
// 4) Row softmax over 2000; writes attn as bf16. grid 16000
// ---------------------------------------------------------------------------
__global__ void __launch_bounds__(256) softmax_kernel() {
    __shared__ float buf[SLEN];
    __shared__ float red[8];
    int tid = threadIdx.x;
    const float* row = g_sim + (size_t)blockIdx.x * SLEN;
    __nv_bfloat16* orow = g_attnB + (size_t)blockIdx.x * SLEN;

    float lmax = -1e30f;
    for (int i = tid; i < SLEN; i += 256) {
        float v = row[i];
        buf[i] = v;
        lmax = fmaxf(lmax, v);
    }
#pragma unroll
    for (int o = 16; o > 0; o >>= 1) lmax = fmaxf(lmax, __shfl_xor_sync(~0u, lmax, o));
    if ((tid & 31) == 0) red[tid >> 5] = lmax;
    __syncthreads();
    float bmax = red[0];
#pragma unroll
    for (int w = 1; w < 8; w++) bmax = fmaxf(bmax, red[w]);

    float lsum = 0.f;
    for (int i = tid; i < SLEN; i += 256) {
        float e = __expf(buf[i] - bmax);
        buf[i] = e;
        lsum += e;
    }
#pragma unroll
    for (int o = 16; o > 0; o >>= 1) lsum += __shfl_xor_sync(~0u, lsum, o);
    __syncthreads();
    if ((tid & 31) == 0) red[tid >> 5] = lsum;
    __syncthreads();
    float bsum = 0.f;
#pragma unroll
    for (int w = 0; w < 8; w++) bsum += red[w];
    float inv = 1.f / bsum;
    for (int i = tid; i < SLEN; i += 256)
        orow[i] = __float2bfloat16(buf[i] * inv);
}

// ---------------------------------------------------------------------------
// 5) outT[pair][128][400] = V^T[128,2000] @ attn^T[2000,400], bf16 HMMA,
//    4-buffer cp.async ring, 1 sync/stage, 125 stages of BK=16.
//    grid (4 n-tiles, 1, 40 pairs), 256 threads. 48B pitches.
// ---------------------------------------------------------------------------
#define ONSTG 125
#define O_STG 6144           // 128*24*2 bytes per stage

__global__ void __launch_bounds__(256) out_kernel() {
    __shared__ __align__(16) __nv_bfloat16 As[4][128][24];  // [ch][s], 48B pitch
    __shared__ __align__(16) __nv_bfloat16 Bs[4][128][24];  // [qpx][s], 48B pitch
    int tid = threadIdx.x, lane = tid & 31, warp = tid >> 5;
    int wm = warp & 1, wn = warp >> 1;   // wn 0..3
    int pair = blockIdx.z;
    int n0 = blockIdx.x * 128;
    const __nv_bfloat16* Vh = g_bufVh + (size_t)(8 + pair * 5) * 51200;
    const __nv_bfloat16* attn = g_attnB + (size_t)pair * 400 * SLEN;

    int arow = tid >> 1, seg = tid & 1;
    int bq = n0 + arow; if (bq > 399) bq = 399;
    uint32_t aDst = (uint32_t)__cvta_generic_to_shared(&As[0][arow][seg * 8]);
    uint32_t bDst = (uint32_t)__cvta_generic_to_shared(&Bs[0][arow][seg * 8]);

    float acc[4][4][4];
#pragma unroll
    for (int i = 0; i < 4; i++)
#pragma unroll
        for (int j = 0; j < 4; j++)
#pragma unroll
            for (int c = 0; c < 4; c++) acc[i][j][c] = 0.f;

    auto issue = [&](int s) {
        int buf = s & 3;
        int j = s / 25;
        int pj0 = (s - j * 25) * 16;
        cpa16(aDst + buf * O_STG, Vh + (size_t)j * 51200 + (size_t)arow * 400 + pj0 + seg * 8);
        cpa16(bDst + buf * O_STG, attn + (size_t)bq * SLEN + s * 16 + seg * 8);
    };

    issue(0); cpa_commit();
    issue(1); cpa_commit();

    uint32_t aLd = (uint32_t)__cvta_generic_to_shared(
        &As[0][wm * 64 + (lane & 15)][0]) + (lane >> 4) * 16;
    uint32_t bLd = (uint32_t)__cvta_generic_to_shared(
        &Bs[0][wn * 32 + (lane & 7) + ((lane >> 4) & 1) * 8][0]) + ((lane >> 3) & 1) * 16;

    for (int s = 0; s < ONSTG; s++) {
        int buf = s & 3;
        if (s + 2 < ONSTG) issue(s + 2);
        cpa_commit();
        cpa_wait2();
        __syncthreads();

        uint32_t a[4][4];
#pragma unroll
        for (int mi = 0; mi < 4; mi++)
            ldsm4(a[mi], aLd + buf * O_STG + mi * 768);
        uint32_t b[4][2];
#pragma unroll
        for (int h = 0; h < 2; h++) {
            uint32_t d[4];
            ldsm4(d, bLd + buf * O_STG + h * 768);
            b[2 * h][0] = d[0];
            b[2 * h][1] = d[1];
            b[2 * h + 1][0] = d[2];
            b[2 * h + 1][1] = d[3];
        }
#pragma unroll
        for (int mi = 0; mi < 4; mi++)
#pragma unroll
            for (int ni = 0; ni < 4; ni++)
                mma16(acc[mi][ni], a[mi], b[ni]);
    }

    int r = lane >> 2, t = lane & 3;
    float* op = g_outT + (size_t)pair * 128 * 400;
#pragma unroll
    for (int mi = 0; mi < 4; mi++)
#pragma unroll
        for (int ni = 0; ni < 4; ni++)
#pragma unroll
            for (int ci = 0; ci < 4; ci++) {
                int row = wm * 64 + mi * 16 + r + ((ci & 2) ? 8 : 0);   // channel
                int col = n0 + wn * 32 + ni * 8 + 2 * t + (ci & 1);     // pixel
                if (col < 400)
                    op[(size_t)row * 400 + col] = acc[mi][ni][ci];
            }
}

// ---------------------------------------------------------------------------
// 6) result[pair] = -sum((qv - out)^2) / 400. grid 40.
// ---------------------------------------------------------------------------
__global__ void __launch_bounds__(256) dist_kernel(float* __restrict__ out) {
    __shared__ float red[8];
    int pair = blockIdx.x, tid = threadIdx.x;
    int b = pair / 5;
    const float* qv = g_bufV + (size_t)b * 128 * 400;
    const float* ot = g_outT + (size_t)pair * 128 * 400;
    float s = 0.f;
    for (int i = tid; i < 51200; i += 256) {
        float d = qv[i] - ot[i];
        s += d * d;
    }
#pragma unroll
    for (int o = 16; o > 0; o >>= 1) s += __shfl_xor_sync(~0u, s, o);
    if ((tid & 31) == 0) red[tid >> 5] = s;
    __syncthreads();
    if (tid == 0) {
        float tot = 0.f;
#pragma unroll
        for (int w = 0; w < 8; w++) tot += red[w];
        out[pair] = -(tot / 400.f);
    }
}

extern "C" void kernel_launch(void* const* d_in, const int* in_sizes, int n_in,
                              void* d_out, int out_size) {
    const float* q   = (const float*)d_in[0];
    const float* s   = (const float*)d_in[1];
    const float* wqk = (const float*)d_in[2];
    const float* wv  = (const float*)d_in[3];
    const float* wms = (const float*)d_in[4];

    cudaFuncSetAttribute(conv_kernel, cudaFuncAttributeMaxDynamicSharedMemorySize,
                         (int)sizeof(ConvSmem));

    nhwc_kernel<<<dim3(53, 16, 208), dim3(32, 8)>>>(q, s);
    fuse_kernel<<<288, 256>>>(wqk, wv, wms);
    repack_kernel<<<4608, 256>>>();
    conv_kernel<<<650, 512, sizeof(ConvSmem)>>>();
    sim_kernel<<<dim3(16, 4, 40), 256>>>();
    softmax_kernel<<<16000, 256>>>();
    out_kernel<<<dim3(4, 1, 40), 256>>>();
    dist_kernel<<<40, 256>>>((float*)d_out);
}

// round 16
// speedup vs baseline: 1.2551x; 1.2551x over previous
#include <cuda_runtime.h>
#include <cuda_bf16.h>
#include <cstdint>

// ---------------------------------------------------------------------------
// Problem constants
// ---------------------------------------------------------------------------
#define IMG_STRIDE 860672   // 512*41*41
#define KDIM 4608           // 512*9
#define NPAIR 40            // b*k = 8*5
#define SLEN 2000           // n*h*w = 5*400

// Static scratch (no dynamic allocation allowed)
__device__ __nv_bfloat16 g_nhwc[(size_t)208 * 1681 * 512];  // input, [img][px][ch] bf16
__device__ float    g_wF[KDIM * 256];                       // fused weights fp32, [k][n]
__device__ uint32_t g_wB[9 * 256 * 256];                    // fused weights bf16x2, [tap][cpair][n]
__device__ uint32_t g_bufK[(size_t)208 * 400 * 128];        // K-proj, [img][px][ch], tf32 bits
__device__ float    g_bufV[(size_t)208 * 128 * 400];        // V-proj, [img][ch][px], fp32
__device__ __nv_bfloat16 g_bufVh[(size_t)208 * 128 * 400];  // V-proj bf16, [img][ch][px]
__device__ float    g_sim[(size_t)NPAIR * 400 * SLEN];      // sim, [pair][qpx][s]
__device__ __nv_bfloat16 g_attnB[(size_t)NPAIR * 400 * SLEN]; // attn bf16, [pair][qpx][s]
__device__ float    g_outT[(size_t)NPAIR * 128 * 400];      // attn@V, [pair][ch][px]

__device__ __forceinline__ uint32_t f2tf(float x) {
    uint32_t r;
    asm("cvt.rna.tf32.f32 %0, %1;" : "=r"(r) : "f"(x));
    return r;
}

__device__ __forceinline__ void cpa16(uint32_t dst, const void* src) {
    asm volatile("cp.async.cg.shared.global [%0], [%1], 16;\n" :: "r"(dst), "l"(src));
}
__device__ __forceinline__ void cpa_commit() { asm volatile("cp.async.commit_group;\n"); }
__device__ __forceinline__ void cpa_wait2() { asm volatile("cp.async.wait_group 2;\n"); }

__device__ __forceinline__ void ldsm4(uint32_t* d, uint32_t addr) {
    asm volatile("ldmatrix.sync.aligned.m8n8.x4.shared.b16 {%0,%1,%2,%3}, [%4];\n"
                 : "=r"(d[0]), "=r"(d[1]), "=r"(d[2]), "=r"(d[3]) : "r"(addr));
}

// tf32 m16n8k8 (sim GEMM)
__device__ __forceinline__ void mma8(float* c, const uint32_t* a, const uint32_t* b) {
    asm volatile(
        "mma.sync.aligned.m16n8k8.row.col.f32.tf32.tf32.f32 "
        "{%0,%1,%2,%3},{%4,%5,%6,%7},{%8,%9},{%0,%1,%2,%3};\n"
        : "+f"(c[0]), "+f"(c[1]), "+f"(c[2]), "+f"(c[3])
        : "r"(a[0]), "r"(a[1]), "r"(a[2]), "r"(a[3]), "r"(b[0]), "r"(b[1]));
}

// bf16 m16n8k16 (conv + out mainloops)
__device__ __forceinline__ void mma16(float* c, const uint32_t* a, const uint32_t* b) {
    asm volatile(
        "mma.sync.aligned.m16n8k16.row.col.f32.bf16.bf16.f32 "
        "{%0,%1,%2,%3},{%4,%5,%6,%7},{%8,%9},{%0,%1,%2,%3};\n"
        : "+f"(c[0]), "+f"(c[1]), "+f"(c[2]), "+f"(c[3])
        : "r"(a[0]), "r"(a[1]), "r"(a[2]), "r"(a[3]), "r"(b[0]), "r"(b[1]));
}

// Warp computes a 64x32 tile of C from As[16][128] x Bs[16][128] (tf32 k-major smem).
__device__ __forceinline__ void mma_block(const uint32_t (*As)[132], const uint32_t (*Bs)[132],
                                          float acc[4][4][4], int wm, int wn, int lane) {
    int r = lane >> 2, t = lane & 3;
#pragma unroll
    for (int ks = 0; ks < 2; ks++) {
        int kb = ks * 8;
        uint32_t a[4][4], b[4][2];
#pragma unroll
        for (int mi = 0; mi < 4; mi++) {
            int mb = wm * 64 + mi * 16 + r;
            a[mi][0] = As[kb + t][mb];
            a[mi][1] = As[kb + t][mb + 8];
            a[mi][2] = As[kb + t + 4][mb];
            a[mi][3] = As[kb + t + 4][mb + 8];
        }
#pragma unroll
        for (int ni = 0; ni < 4; ni++) {
            int nb = wn * 32 + ni * 8 + r;
            b[ni][0] = Bs[kb + t][nb];
            b[ni][1] = Bs[kb + t + 4][nb];
        }
#pragma unroll
        for (int mi = 0; mi < 4; mi++)
#pragma unroll
            for (int ni = 0; ni < 4; ni++)
                mma8(acc[mi][ni], a[mi], b[ni]);
    }
}

// ---------------------------------------------------------------------------
// 0) NCHW fp32 -> NHWC bf16 transpose. grid (53, 16, 208), block (32, 8).
// ---------------------------------------------------------------------------
__global__ void __launch_bounds__(256) nhwc_kernel(const float* __restrict__ q,
                                                   const float* __restrict__ s) {
    __shared__ float tile[32][33];
    int img = blockIdx.z;
    int px0 = blockIdx.x * 32, c0 = blockIdx.y * 32;
    const float* src = (img < 8) ? (q + (size_t)img * IMG_STRIDE)
                                 : (s + (size_t)(img - 8) * IMG_STRIDE);
    int tx = threadIdx.x, ty = threadIdx.y;
#pragma unroll
    for (int i = 0; i < 4; i++) {
        int c = c0 + ty + i * 8, px = px0 + tx;
        if (px < 1681) tile[ty + i * 8][tx] = src[(size_t)c * 1681 + px];
    }
    __syncthreads();
#pragma unroll
    for (int i = 0; i < 4; i++) {
        int px = px0 + ty + i * 8, c = c0 + tx;
        if (px < 1681)
            g_nhwc[((size_t)img * 1681 + px) * 512 + c] = __float2bfloat16(tile[tx][ty + i * 8]);
    }
}

// ---------------------------------------------------------------------------
// 1) Fuse weights: wF[k][n] = sum_e proj[n][e] * w_ms[e*4608 + k]
// ---------------------------------------------------------------------------
__global__ void __launch_bounds__(256) fuse_kernel(const float* __restrict__ wqk,
                                                   const float* __restrict__ wv,
                                                   const float* __restrict__ wms) {
    __shared__ float projS[256][17];
    __shared__ float msS[16][17];
    int tid = threadIdx.x;
    int k0 = blockIdx.x * 16;
    const float* prow = (tid < 128) ? (wqk + (size_t)tid * 512)
                                    : (wv + (size_t)(tid - 128) * 512);
    float acc[16];
#pragma unroll
    for (int i = 0; i < 16; i++) acc[i] = 0.f;

    int le = tid >> 4, lk = tid & 15;
    for (int e0 = 0; e0 < 512; e0 += 16) {
        __syncthreads();
#pragma unroll
        for (int q4 = 0; q4 < 4; q4++) {
            float4 d = *(const float4*)(prow + e0 + q4 * 4);
            projS[tid][q4 * 4 + 0] = d.x;
            projS[tid][q4 * 4 + 1] = d.y;
            projS[tid][q4 * 4 + 2] = d.z;
            projS[tid][q4 * 4 + 3] = d.w;
        }
        msS[le][lk] = wms[(size_t)(e0 + le) * KDIM + k0 + lk];
        __syncthreads();
#pragma unroll
        for (int e = 0; e < 16; e++) {
            float a = projS[tid][e];
#pragma unroll
            for (int kk = 0; kk < 16; kk++) acc[kk] += a * msS[e][kk];
        }
    }
#pragma unroll
    for (int kk = 0; kk < 16; kk++)
        g_wF[(size_t)(k0 + kk) * 256 + tid] = acc[kk];
}

// ---------------------------------------------------------------------------
// 1b) Repack weights to bf16x2 [tap][cpair][n]. Original k = c*9 + tap.
// ---------------------------------------------------------------------------
__global__ void __launch_bounds__(256) repack_kernel() {
    int idx = blockIdx.x * 256 + threadIdx.x;   // < 9*65536
    int n = idx & 255;
    int cp = (idx >> 8) & 255;
    int tap = idx >> 16;
    if (tap >= 9) return;
    float lo = g_wF[(size_t)(2 * cp * 9 + tap) * 256 + n];
    float hi = g_wF[(size_t)((2 * cp + 1) * 9 + tap) * 256 + n];
    __nv_bfloat162 p = __floats2bfloat162_rn(lo, hi);
    g_wB[idx] = *(uint32_t*)&p;
}

// ---------------------------------------------------------------------------
// 2) Implicit-GEMM conv (bf16 HMMA, 4-buffer cp.async pipeline, 1 sync/stage):
//    ROUND-8 structure (measured 576us): grid 650 m-tiles, 512 threads,
//    BM=128, BN=256, BK=32, warp tile 64x32, LDSM A + scalar-LDS B.
//    Only change vs r8: epilogue additionally stores bf16 V.
// ---------------------------------------------------------------------------
#define CNSTG 144
#define A_STG 10240          // 128*40*2 bytes per A stage
#define B_STG 16896          // 16*264*4 bytes per B stage

struct ConvSmem {
    __nv_bfloat16 A[4][128][40];  // [m][ch] +8 pad (row stride 80B)
    uint32_t      B[4][16][264];  // [cpair][n] bf16x2, +8 pad
};

__global__ void __launch_bounds__(512) conv_kernel() {
    extern __shared__ __align__(16) char smem_raw[];
    ConvSmem& sm = *reinterpret_cast<ConvSmem*>(smem_raw);

    int tid = threadIdx.x, lane = tid & 31, warp = tid >> 5;
    int wm = warp & 1, wn = warp >> 1;   // wm: 0..1, wn: 0..7
    int r = lane >> 2, t = lane & 3;

    // A-load mapping: one 16B cp.async per thread per stage
    int arow = tid >> 2, aseg = tid & 3;
    const __nv_bfloat16* apix;
    {
        int m = blockIdx.x * 128 + arow;
        int img = m / 400;
        int p = m - img * 400;
        int oy = p / 20, ox = p - oy * 20;
        apix = g_nhwc + ((size_t)img * 1681 + (size_t)(2 * oy) * 41 + 2 * ox) * 512 + aseg * 8;
    }
    uint32_t aDst = (uint32_t)__cvta_generic_to_shared(&sm.A[0][arow][aseg * 8]);

    // B-load mapping: 2 x 16B per thread (rows bcp, bcp+8)
    int bcp = tid >> 6, bn4 = (tid & 63) * 4;   // bcp 0..7
    uint32_t bDst = (uint32_t)__cvta_generic_to_shared(&sm.B[0][bcp][bn4]);

    float acc[4][4][4];
#pragma unroll
    for (int i = 0; i < 4; i++)
#pragma unroll
        for (int j = 0; j < 4; j++)
#pragma unroll
            for (int c = 0; c < 4; c++) acc[i][j][c] = 0.f;

    auto issue = [&](int s) {
        int buf = s & 3;
        int tap = s >> 4;
        int dy = tap / 3, dx = tap - 3 * dy;
        int po = (dy * 41 + dx) * 512 + ((s & 15) << 5);
        cpa16(aDst + buf * A_STG, apix + po);
        const uint32_t* bs = g_wB + (size_t)tap * 65536 + (size_t)((s & 15) * 16 + bcp) * 256 + bn4;
        uint32_t bd = bDst + buf * B_STG;
#pragma unroll
        for (int i = 0; i < 2; i++)
            cpa16(bd + i * 8448, bs + (size_t)i * 2048);   // +8 cpair rows
    };

    issue(0); cpa_commit();
    issue(1); cpa_commit();

    // LDSM lane address base: row = wm*64 + (lane&15), col base = (lane>>4)*8
    uint32_t aLd = (uint32_t)__cvta_generic_to_shared(
        &sm.A[0][wm * 64 + (lane & 15)][(lane >> 4) * 8]);

    for (int s = 0; s < CNSTG; s++) {
        int buf = s & 3;
        if (s + 2 < CNSTG) issue(s + 2);
        cpa_commit();
        cpa_wait2();
        __syncthreads();

#pragma unroll
        for (int ks = 0; ks < 2; ks++) {
            uint32_t a[4][4];
#pragma unroll
            for (int mi = 0; mi < 4; mi++)
                ldsm4(a[mi], aLd + buf * A_STG + mi * 1280 + ks * 32);
            uint32_t b[4][2];
#pragma unroll
            for (int ni = 0; ni < 4; ni++) {
                int N = wn * 32 + ni * 8 + r;
                b[ni][0] = sm.B[buf][ks * 8 + t][N];
                b[ni][1] = sm.B[buf][ks * 8 + 4 + t][N];
            }
#pragma unroll
            for (int mi = 0; mi < 4; mi++)
#pragma unroll
                for (int ni = 0; ni < 4; ni++)
                    mma16(acc[mi][ni], a[mi], b[ni]);
        }
    }

    // Epilogue: cols 0..127 -> K-proj (tf32, px-major); 128..255 -> V (fp32 + bf16, ch-major)
#pragma unroll
    for (int mi = 0; mi < 4; mi++)
#pragma unroll
        for (int ni = 0; ni < 4; ni++)
#pragma unroll
            for (int ci = 0; ci < 4; ci++) {
                int row = blockIdx.x * 128 + wm * 64 + mi * 16 + r + ((ci & 2) ? 8 : 0);
                int col = wn * 32 + ni * 8 + 2 * t + (ci & 1);
                int im = row / 400;
                int pp = row - im * 400;
                float v = acc[mi][ni][ci];
                if (col < 128) {
                    g_bufK[((size_t)im * 400 + pp) * 128 + col] = f2tf(v);
                } else {
                    size_t o = ((size_t)im * 128 + (col - 128)) * 400 + pp;
                    g_bufV[o] = v;
                    g_bufVh[o] = __float2bfloat16(v);
                }
            }
}

// ---------------------------------------------------------------------------
// 3) sim[pair][400][2000] = (Q[400,128] @ K^T[128,2000]) * 128^-0.5
// ---------------------------------------------------------------------------
__global__ void __launch_bounds__(256) sim_kernel() {
    __shared__ uint32_t As[16][132];
    __shared__ uint32_t Bs[16][132];
    int tid = threadIdx.x, lane = tid & 31, warp = tid >> 5;
    int wm = warp & 1, wn = warp >> 1;
    int pair = blockIdx.z;
    int b = pair / 5;
    const uint32_t* Q = g_bufK + (size_t)b * 400 * 128;
    const uint32_t* Kp = g_bufK + (size_t)(8 + pair * 5) * 400 * 128;
    int m0 = blockIdx.y * 128, n0 = blockIdx.x * 128;

    float acc[4][4][4];
#pragma unroll
    for (int i = 0; i < 4; i++)
#pragma unroll
        for (int j = 0; j < 4; j++)
#pragma unroll
            for (int c = 0; c < 4; c++) acc[i][j][c] = 0.f;

    for (int k0 = 0; k0 < 128; k0 += 16) {
#pragma unroll
        for (int i = 0; i < 2; i++) {
            int v = tid + 256 * i;
            int l = v >> 2, kq = v & 3;
            uint4 d = make_uint4(0u, 0u, 0u, 0u);
            if (m0 + l < 400) d = *(const uint4*)(Q + (size_t)(m0 + l) * 128 + k0 + kq * 4);
            As[kq * 4 + 0][l] = d.x;
            As[kq * 4 + 1][l] = d.y;
            As[kq * 4 + 2][l] = d.z;
            As[kq * 4 + 3][l] = d.w;
        }
#pragma unroll
        for (int i = 0; i < 2; i++) {
            int v = tid + 256 * i;
            int l = v >> 2, kq = v & 3;
            uint4 d = make_uint4(0u, 0u, 0u, 0u);
            if (n0 + l < SLEN) d = *(const uint4*)(Kp + (size_t)(n0 + l) * 128 + k0 + kq * 4);
            Bs[kq * 4 + 0][l] = d.x;
            Bs[kq * 4 + 1][l] = d.y;
            Bs[kq * 4 + 2][l] = d.z;
            Bs[kq * 4 + 3][l] = d.w;
        }
        __syncthreads();
        mma_block(As, Bs, acc, wm, wn, lane);
        __syncthreads();
    }

    const float scale = 0.08838834764831845f;  // 128^-0.5
    int r = lane >> 2, t = lane & 3;
    float* simp = g_sim + (size_t)pair * 400 * SLEN;
#pragma unroll
    for (int mi = 0; mi < 4; mi++)
#pragma unroll
        for (int ni = 0; ni < 4; ni++)
#pragma unroll
            for (int ci = 0; ci < 4; ci++) {
                int row = m0 + wm * 64 + mi * 16 + r + ((ci & 2) ? 8 : 0);
                int col = n0 + wn * 32 + ni * 8 + 2 * t + (ci & 1);
                if (row < 400 && col < SLEN)
                    simp[(size_t)row * SLEN + col] = acc[mi][ni][ci] * scale;
            }
}

// ---------------------------------------------------------------------------
// 4) Row softmax over 2000; writes attn as bf16. grid 16000
// ---------------------------------------------------------------------------
__global__ void __launch_bounds__(256) softmax_kernel() {
    __shared__ float buf[SLEN];
    __shared__ float red[8];
    int tid = threadIdx.x;
    const float* row = g_sim + (size_t)blockIdx.x * SLEN;
    __nv_bfloat16* orow = g_attnB + (size_t)blockIdx.x * SLEN;

    float lmax = -1e30f;
    for (int i = tid; i < SLEN; i += 256) {
        float v = row[i];
        buf[i] = v;
        lmax = fmaxf(lmax, v);
    }
#pragma unroll
    for (int o = 16; o > 0; o >>= 1) lmax = fmaxf(lmax, __shfl_xor_sync(~0u, lmax, o));
    if ((tid & 31) == 0) red[tid >> 5] = lmax;
    __syncthreads();
    float bmax = red[0];
#pragma unroll
    for (int w = 1; w < 8; w++) bmax = fmaxf(bmax, red[w]);

    float lsum = 0.f;
    for (int i = tid; i < SLEN; i += 256) {
        float e = __expf(buf[i] - bmax);
        buf[i] = e;
        lsum += e;
    }
#pragma unroll
    for (int o = 16; o > 0; o >>= 1) lsum += __shfl_xor_sync(~0u, lsum, o);
    __syncthreads();
    if ((tid & 31) == 0) red[tid >> 5] = lsum;
    __syncthreads();
    float bsum = 0.f;
#pragma unroll
    for (int w = 0; w < 8; w++) bsum += red[w];
    float inv = 1.f / bsum;
    for (int i = tid; i < SLEN; i += 256)
        orow[i] = __float2bfloat16(buf[i] * inv);
}

// ---------------------------------------------------------------------------
// 5) outT[pair][128][400] = V^T[128,2000] @ attn^T[2000,400], bf16 HMMA,
//    4-buffer cp.async ring, 1 sync/stage, 125 stages of BK=16.
//    grid (4 n-tiles, 1, 40 pairs), 256 threads. 48B pitches.
// ---------------------------------------------------------------------------
#define ONSTG 125
#define O_STG 6144           // 128*24*2 bytes per stage

__global__ void __launch_bounds__(256) out_kernel() {
    __shared__ __align__(16) __nv_bfloat16 As[4][128][24];  // [ch][s], 48B pitch
    __shared__ __align__(16) __nv_bfloat16 Bs[4][128][24];  // [qpx][s], 48B pitch
    int tid = threadIdx.x, lane = tid & 31, warp = tid >> 5;
    int wm = warp & 1, wn = warp >> 1;   // wn 0..3
    int pair = blockIdx.z;
    int n0 = blockIdx.x * 128;
    const __nv_bfloat16* Vh = g_bufVh + (size_t)(8 + pair * 5) * 51200;
    const __nv_bfloat16* attn = g_attnB + (size_t)pair * 400 * SLEN;

    int arow = tid >> 1, seg = tid & 1;
    int bq = n0 + arow; if (bq > 399) bq = 399;
    uint32_t aDst = (uint32_t)__cvta_generic_to_shared(&As[0][arow][seg * 8]);
    uint32_t bDst = (uint32_t)__cvta_generic_to_shared(&Bs[0][arow][seg * 8]);

    float acc[4][4][4];
#pragma unroll
    for (int i = 0; i < 4; i++)
#pragma unroll
        for (int j = 0; j < 4; j++)
#pragma unroll
            for (int c = 0; c < 4; c++) acc[i][j][c] = 0.f;

    auto issue = [&](int s) {
        int buf = s & 3;
        int j = s / 25;
        int pj0 = (s - j * 25) * 16;
        cpa16(aDst + buf * O_STG, Vh + (size_t)j * 51200 + (size_t)arow * 400 + pj0 + seg * 8);
        cpa16(bDst + buf * O_STG, attn + (size_t)bq * SLEN + s * 16 + seg * 8);
    };

    issue(0); cpa_commit();
    issue(1); cpa_commit();

    uint32_t aLd = (uint32_t)__cvta_generic_to_shared(
        &As[0][wm * 64 + (lane & 15)][0]) + (lane >> 4) * 16;
    uint32_t bLd = (uint32_t)__cvta_generic_to_shared(
        &Bs[0][wn * 32 + (lane & 7) + ((lane >> 4) & 1) * 8][0]) + ((lane >> 3) & 1) * 16;

    for (int s = 0; s < ONSTG; s++) {
        int buf = s & 3;
        if (s + 2 < ONSTG) issue(s + 2);
        cpa_commit();
        cpa_wait2();
        __syncthreads();

        uint32_t a[4][4];
#pragma unroll
        for (int mi = 0; mi < 4; mi++)
            ldsm4(a[mi], aLd + buf * O_STG + mi * 768);
        uint32_t b[4][2];
#pragma unroll
        for (int h = 0; h < 2; h++) {
            uint32_t d[4];
            ldsm4(d, bLd + buf * O_STG + h * 768);
            b[2 * h][0] = d[0];
            b[2 * h][1] = d[1];
            b[2 * h + 1][0] = d[2];
            b[2 * h + 1][1] = d[3];
        }
#pragma unroll
        for (int mi = 0; mi < 4; mi++)
#pragma unroll
            for (int ni = 0; ni < 4; ni++)
                mma16(acc[mi][ni], a[mi], b[ni]);
    }

    int r = lane >> 2, t = lane & 3;
    float* op = g_outT + (size_t)pair * 128 * 400;
#pragma unroll
    for (int mi = 0; mi < 4; mi++)
#pragma unroll
        for (int ni = 0; ni < 4; ni++)
#pragma unroll
            for (int ci = 0; ci < 4; ci++) {
                int row = wm * 64 + mi * 16 + r + ((ci & 2) ? 8 : 0);   // channel
                int col = n0 + wn * 32 + ni * 8 + 2 * t + (ci & 1);     // pixel
                if (col < 400)
                    op[(size_t)row * 400 + col] = acc[mi][ni][ci];
            }
}

// ---------------------------------------------------------------------------
// 6) result[pair] = -sum((qv - out)^2) / 400. grid 40.
// ---------------------------------------------------------------------------
__global__ void __launch_bounds__(256) dist_kernel(float* __restrict__ out) {
    __shared__ float red[8];
    int pair = blockIdx.x, tid = threadIdx.x;
    int b = pair / 5;
    const float* qv = g_bufV + (size_t)b * 128 * 400;
    const float* ot = g_outT + (size_t)pair * 128 * 400;
    float s = 0.f;
    for (int i = tid; i < 51200; i += 256) {
        float d = qv[i] - ot[i];
        s += d * d;
    }
#pragma unroll
    for (int o = 16; o > 0; o >>= 1) s += __shfl_xor_sync(~0u, s, o);
    if ((tid & 31) == 0) red[tid >> 5] = s;
    __syncthreads();
    if (tid == 0) {
        float tot = 0.f;
#pragma unroll
        for (int w = 0; w < 8; w++) tot += red[w];
        out[pair] = -(tot / 400.f);
    }
}

extern "C" void kernel_launch(void* const* d_in, const int* in_sizes, int n_in,
                              void* d_out, int out_size) {
    const float* q   = (const float*)d_in[0];
    const float* s   = (const float*)d_in[1];
    const float* wqk = (const float*)d_in[2];
    const float* wv  = (const float*)d_in[3];
    const float* wms = (const float*)d_in[4];

    cudaFuncSetAttribute(conv_kernel, cudaFuncAttributeMaxDynamicSharedMemorySize,
                         (int)sizeof(ConvSmem));

    nhwc_kernel<<<dim3(53, 16, 208), dim3(32, 8)>>>(q, s);
    fuse_kernel<<<288, 256>>>(wqk, wv, wms);
    repack_kernel<<<2304, 256>>>();
    conv_kernel<<<650, 512, sizeof(ConvSmem)>>>();
    sim_kernel<<<dim3(16, 4, 40), 256>>>();
    softmax_kernel<<<16000, 256>>>();
    out_kernel<<<dim3(4, 1, 40), 256>>>();
    dist_kernel<<<40, 256>>>((float*)d_out);
}